// round 2
// baseline (speedup 1.0000x reference)
#include <cuda_runtime.h>
#include <cuda_bf16.h>

#define N_NODES 50000
#define N_GRAPHS 1024
#define MAXC 256

// ---------------- static scratch (no allocation allowed) ----------------
__device__ float d_h  [N_NODES * MAXC];   // g = dinv * (A @ W)   (gather source)
__device__ float d_agg[N_NODES * MAXC];   // scatter accumulator (init = self-loop g)
__device__ float d_res[N_NODES * MAXC];   // residual branch
__device__ float d_xa [N_NODES * MAXC];   // x1 / x3
__device__ float d_xb [N_NODES * MAXC];   // x2
__device__ float d_deg [N_NODES];
__device__ float d_dinv[N_NODES];
__device__ float d_fp  [N_GRAPHS * MAXC];
__device__ float d_fg  [N_GRAPHS * MAXC];
__device__ float d_sums[N_GRAPHS * MAXC];
__device__ float d_cnt [N_GRAPHS];

// ---------------- init / degree ----------------
__global__ void zero_kernel() {
    int total = N_NODES + N_GRAPHS * MAXC + N_GRAPHS;
    for (int i = blockIdx.x * blockDim.x + threadIdx.x; i < total;
         i += gridDim.x * blockDim.x) {
        if (i < N_NODES) d_deg[i] = 0.0f;
        else if (i < N_NODES + N_GRAPHS * MAXC) d_sums[i - N_NODES] = 0.0f;
        else d_cnt[i - N_NODES - N_GRAPHS * MAXC] = 0.0f;
    }
}

// NOTE: edge_index / batch are int32 on device (JAX x64 disabled downcasts
// jnp.int64 -> int32). Reading them as long long caused the round-1 IMA.
__global__ void deg_kernel(const int* __restrict__ ei, int E) {
    int e = blockIdx.x * blockDim.x + threadIdx.x;
    if (e < E) {
        unsigned d = (unsigned)ei[E + e];
        if (d < N_NODES) atomicAdd(&d_deg[d], 1.0f);
    }
}

__global__ void dinv_kernel() {
    int i = blockIdx.x * blockDim.x + threadIdx.x;
    if (i < N_NODES) d_dinv[i] = rsqrtf(d_deg[i] + 1.0f);
}

// ---------------- tiled SGEMM with fused epilogue ----------------
// C[M,N] = A[M,K] @ W[K,N]; then v *= rowscale[row] (opt); v += bias[col] (opt);
// relu (opt); store C and optionally duplicate into C2 (scatter-accumulator init).
template<int BM, int BN, int BK>
__global__ __launch_bounds__(256)
void sgemm_kernel(const float* __restrict__ A, const float* __restrict__ W,
                  const float* __restrict__ bias, const float* __restrict__ rowscale,
                  float* __restrict__ C, float* __restrict__ C2,
                  int M, int N, int K, int do_relu)
{
    __shared__ float As[BM][BK + 1];
    __shared__ float Bs[BK][BN + 1];
    const int TM = 4, TN = 4;
    int tid = threadIdx.x;                 // 256 threads = 16 x 16
    int tx  = tid % (BN / TN);
    int ty  = tid / (BN / TN);
    int row0 = blockIdx.y * BM;
    int col0 = blockIdx.x * BN;

    float acc[TM][TN];
    #pragma unroll
    for (int i = 0; i < TM; i++)
        #pragma unroll
        for (int j = 0; j < TN; j++) acc[i][j] = 0.0f;

    for (int k0 = 0; k0 < K; k0 += BK) {
        for (int i = tid; i < BM * BK; i += 256) {
            int r = i / BK, c = i % BK;
            int gr = row0 + r, gc = k0 + c;
            As[r][c] = (gr < M && gc < K) ? A[(size_t)gr * K + gc] : 0.0f;
        }
        for (int i = tid; i < BK * BN; i += 256) {
            int r = i / BN, c = i % BN;
            int gr = k0 + r, gc = col0 + c;
            Bs[r][c] = (gr < K && gc < N) ? W[(size_t)gr * N + gc] : 0.0f;
        }
        __syncthreads();
        #pragma unroll
        for (int kk = 0; kk < BK; kk++) {
            float a[TM], b[TN];
            #pragma unroll
            for (int i = 0; i < TM; i++) a[i] = As[ty * TM + i][kk];
            #pragma unroll
            for (int j = 0; j < TN; j++) b[j] = Bs[kk][tx * TN + j];
            #pragma unroll
            for (int i = 0; i < TM; i++)
                #pragma unroll
                for (int j = 0; j < TN; j++) acc[i][j] += a[i] * b[j];
        }
        __syncthreads();
    }

    #pragma unroll
    for (int i = 0; i < TM; i++) {
        int gr = row0 + ty * TM + i;
        if (gr >= M) continue;
        float rs = rowscale ? rowscale[gr] : 1.0f;
        #pragma unroll
        for (int j = 0; j < TN; j++) {
            int gc = col0 + tx * TN + j;
            if (gc >= N) continue;
            float v = acc[i][j] * rs;
            if (bias) v += bias[gc];
            if (do_relu) v = fmaxf(v, 0.0f);
            C[(size_t)gr * N + gc] = v;
            if (C2) C2[(size_t)gr * N + gc] = v;
        }
    }
}

// ---------------- edge scatter: agg[dst] += g[src] ----------------
// One warp per edge. Vectorized float4 reduction (red.global.add.v4.f32, sm_90+).
__global__ void scatter_kernel(const int* __restrict__ ei, int E, int C) {
    int gw   = (blockIdx.x * blockDim.x + threadIdx.x) >> 5;
    int lane = threadIdx.x & 31;
    int nw   = (gridDim.x * blockDim.x) >> 5;
    for (int e = gw; e < E; e += nw) {
        unsigned s = (unsigned)ei[e];
        unsigned d = (unsigned)ei[E + e];
        if (s >= N_NODES || d >= N_NODES) continue;
        const float4* gs = (const float4*)(d_h + (size_t)s * C);
        float* ad = d_agg + (size_t)d * C;
        int c4 = C >> 2;
        for (int c = lane; c < c4; c += 32) {
            float4 v = gs[c];
            float* p = ad + 4 * c;
            asm volatile("red.global.add.v4.f32 [%0], {%1, %2, %3, %4};"
                         :: "l"(p), "f"(v.x), "f"(v.y), "f"(v.z), "f"(v.w)
                         : "memory");
        }
    }
}

// ---------------- combine: x_next = relu(dinv*agg + b (+ res)) ----------------
__global__ void combine_kernel(const float* __restrict__ bias,
                               const float* __restrict__ res,
                               float* __restrict__ out, int C) {
    size_t i = (size_t)blockIdx.x * blockDim.x + threadIdx.x;
    size_t total = (size_t)N_NODES * C;
    if (i >= total) return;
    int row = (int)(i / C);
    int col = (int)(i % C);
    float v = d_dinv[row] * d_agg[i] + bias[col];
    if (res) v += res[i];
    out[i] = fmaxf(v, 0.0f);
}

// ---------------- fused softmax-attention + mean-pool accumulate ----------------
// warp per node: attn = softmax(scores row); sums[batch] += attn * x3; cnt[batch]++.
__global__ void pool_kernel(const int* __restrict__ batch) {
    int node = (blockIdx.x * blockDim.x + threadIdx.x) >> 5;
    int lane = threadIdx.x & 31;
    if (node >= N_NODES) return;
    const float* srow = d_h  + (size_t)node * 256;   // attention scores
    const float* xrow = d_xa + (size_t)node * 256;   // x3
    float vals[8];
    float m = -3.0e38f;
    #pragma unroll
    for (int j = 0; j < 8; j++) { vals[j] = srow[lane + 32 * j]; m = fmaxf(m, vals[j]); }
    #pragma unroll
    for (int off = 16; off; off >>= 1) m = fmaxf(m, __shfl_xor_sync(0xffffffffu, m, off));
    float ssum = 0.0f;
    #pragma unroll
    for (int j = 0; j < 8; j++) { vals[j] = __expf(vals[j] - m); ssum += vals[j]; }
    #pragma unroll
    for (int off = 16; off; off >>= 1) ssum += __shfl_xor_sync(0xffffffffu, ssum, off);
    float inv = 1.0f / ssum;
    unsigned b = (unsigned)batch[node];
    if (b >= N_GRAPHS) return;
    float* orow = d_sums + (size_t)b * 256;
    #pragma unroll
    for (int j = 0; j < 8; j++) {
        atomicAdd(orow + lane + 32 * j, vals[j] * inv * xrow[lane + 32 * j]);
    }
    if (lane == 0) atomicAdd(&d_cnt[b], 1.0f);
}

// ---------------- final: out = (pooled + fp + fg) @ Wfc + bfc ----------------
__global__ void final_kernel(const float* __restrict__ Wfc,
                             const float* __restrict__ bfc,
                             float* __restrict__ out) {
    int b    = (blockIdx.x * blockDim.x + threadIdx.x) >> 5;
    int lane = threadIdx.x & 31;
    if (b >= N_GRAPHS) return;
    float invc = 1.0f / fmaxf(d_cnt[b], 1.0f);
    float acc = 0.0f;
    #pragma unroll
    for (int j = lane; j < 256; j += 32) {
        float v = d_sums[b * 256 + j] * invc + d_fp[b * 256 + j] + d_fg[b * 256 + j];
        acc += v * Wfc[j];
    }
    #pragma unroll
    for (int off = 16; off; off >>= 1) acc += __shfl_xor_sync(0xffffffffu, acc, off);
    if (lane == 0) out[b] = acc + bfc[0];
}

// ---------------- launch ----------------
extern "C" void kernel_launch(void* const* d_in, const int* in_sizes, int n_in,
                              void* d_out, int out_size) {
    const float* x     = (const float*)d_in[0];
    const int*   ei    = (const int*)d_in[1];     // int32 (JAX x64 disabled)
    const int*   batch = (const int*)d_in[2];     // int32
    const float* fpf = (const float*)d_in[3];
    const float* fgr = (const float*)d_in[4];
    const float* W1  = (const float*)d_in[5],  *b1  = (const float*)d_in[6];
    const float* W2  = (const float*)d_in[7],  *b2  = (const float*)d_in[8];
    const float* W3  = (const float*)d_in[9],  *b3  = (const float*)d_in[10];
    const float* Wr1 = (const float*)d_in[11], *br1 = (const float*)d_in[12];
    const float* Wr2 = (const float*)d_in[13], *br2 = (const float*)d_in[14];
    const float* Wfp = (const float*)d_in[15], *bfp = (const float*)d_in[16];
    const float* Wfg = (const float*)d_in[17], *bfg = (const float*)d_in[18];
    const float* attn_W = (const float*)d_in[19];
    const float* Wfc = (const float*)d_in[20], *bfc = (const float*)d_in[21];
    float* out = (float*)d_out;
    int E = in_sizes[1] / 2;

    float *ph, *pagg, *pres, *pxa, *pxb, *pdinv, *pfp, *pfg;
    cudaGetSymbolAddress((void**)&ph,   d_h);
    cudaGetSymbolAddress((void**)&pagg, d_agg);
    cudaGetSymbolAddress((void**)&pres, d_res);
    cudaGetSymbolAddress((void**)&pxa,  d_xa);
    cudaGetSymbolAddress((void**)&pxb,  d_xb);
    cudaGetSymbolAddress((void**)&pdinv, d_dinv);
    cudaGetSymbolAddress((void**)&pfp,  d_fp);
    cudaGetSymbolAddress((void**)&pfg,  d_fg);

    const int T = 256;
    auto cdiv = [](int a, int b) { return (a + b - 1) / b; };

    // degrees / dinv / zero accumulators
    zero_kernel<<<cdiv(N_NODES + N_GRAPHS * MAXC + N_GRAPHS, T), T>>>();
    deg_kernel<<<cdiv(E, T), T>>>(ei, E);
    dinv_kernel<<<cdiv(N_NODES, T), T>>>();

    dim3 gN128(128 / 64, cdiv(N_NODES, 64));
    dim3 gN256(256 / 64, cdiv(N_NODES, 64));
    dim3 gB256(256 / 64, cdiv(N_GRAPHS, 64));
    int scatterBlocks = cdiv(E, 8);   // one warp per edge

    // ---- Layer 1: g1 = dinv*(x@W1); scatter; x1 = relu(dinv*agg + b1)
    sgemm_kernel<64,64,16><<<gN128, T>>>(x, W1, nullptr, pdinv, ph, pagg,
                                         N_NODES, 128, 64, 0);
    scatter_kernel<<<scatterBlocks, T>>>(ei, E, 128);
    combine_kernel<<<cdiv(N_NODES * 128, T), T>>>(b1, nullptr, pxa, 128);

    // ---- Layer 2: res = x1@Wr1+br1; g2 = dinv*(x1@W2); scatter; x2 = relu(...)
    sgemm_kernel<64,64,16><<<gN256, T>>>(pxa, Wr1, br1, nullptr, pres, nullptr,
                                         N_NODES, 256, 128, 0);
    sgemm_kernel<64,64,16><<<gN256, T>>>(pxa, W2, nullptr, pdinv, ph, pagg,
                                         N_NODES, 256, 128, 0);
    scatter_kernel<<<scatterBlocks, T>>>(ei, E, 256);
    combine_kernel<<<cdiv(N_NODES * 256, T), T>>>(b2, pres, pxb, 256);

    // ---- Layer 3: res = x2@Wr2+br2; g3 = dinv*(x2@W3); scatter; x3 = relu(...)
    sgemm_kernel<64,64,16><<<gN256, T>>>(pxb, Wr2, br2, nullptr, pres, nullptr,
                                         N_NODES, 256, 256, 0);
    sgemm_kernel<64,64,16><<<gN256, T>>>(pxb, W3, nullptr, pdinv, ph, pagg,
                                         N_NODES, 256, 256, 0);
    scatter_kernel<<<scatterBlocks, T>>>(ei, E, 256);
    combine_kernel<<<cdiv(N_NODES * 256, T), T>>>(b3, pres, pxa, 256);

    // ---- attention scores: s = x3 @ attn_W  (into d_h)
    sgemm_kernel<64,64,16><<<gN256, T>>>(pxa, attn_W, nullptr, nullptr, ph, nullptr,
                                         N_NODES, 256, 256, 0);

    // ---- fingerprint / func-group branches
    sgemm_kernel<64,64,16><<<gB256, T>>>(fpf, Wfp, bfp, nullptr, pfp, nullptr,
                                         N_GRAPHS, 256, 2048, 1);
    sgemm_kernel<64,64,16><<<gB256, T>>>(fgr, Wfg, bfg, nullptr, pfg, nullptr,
                                         N_GRAPHS, 256, 167, 1);

    // ---- softmax-attention mean pool + final projection
    pool_kernel<<<cdiv(N_NODES * 32, T), T>>>(batch);
    final_kernel<<<cdiv(N_GRAPHS * 32, T), T>>>(Wfc, bfc, out);
}

// round 4
// speedup vs baseline: 1.4517x; 1.4517x over previous
#include <cuda_runtime.h>
#include <cuda_bf16.h>

#define N_NODES 50000
#define N_GRAPHS 1024
#define MAXC 256

// ---------------- static scratch (no allocation allowed) ----------------
__device__ float d_h  [N_NODES * MAXC];   // g = dinv * (A @ W)   (gather source)
__device__ float d_agg[N_NODES * MAXC];   // scatter accumulator (init = self-loop g)
__device__ float d_res[N_NODES * MAXC];   // residual branch
__device__ float d_xa [N_NODES * MAXC];   // x1 / x3
__device__ float d_xb [N_NODES * MAXC];   // x2
__device__ float d_deg [N_NODES];
__device__ float d_dinv[N_NODES];
__device__ float d_fp  [N_GRAPHS * MAXC];
__device__ float d_fg  [N_GRAPHS * MAXC];
__device__ float d_sums[N_GRAPHS * MAXC];
__device__ float d_cnt [N_GRAPHS];

// ---------------- init / degree ----------------
__global__ void zero_kernel() {
    int total = N_NODES + N_GRAPHS * MAXC + N_GRAPHS;
    for (int i = blockIdx.x * blockDim.x + threadIdx.x; i < total;
         i += gridDim.x * blockDim.x) {
        if (i < N_NODES) d_deg[i] = 0.0f;
        else if (i < N_NODES + N_GRAPHS * MAXC) d_sums[i - N_NODES] = 0.0f;
        else d_cnt[i - N_NODES - N_GRAPHS * MAXC] = 0.0f;
    }
}

__global__ void deg_kernel(const int* __restrict__ ei, int E) {
    int e = blockIdx.x * blockDim.x + threadIdx.x;
    if (e < E) {
        unsigned d = (unsigned)ei[E + e];
        if (d < N_NODES) atomicAdd(&d_deg[d], 1.0f);
    }
}

__global__ void dinv_kernel() {
    int i = blockIdx.x * blockDim.x + threadIdx.x;
    if (i < N_NODES) d_dinv[i] = rsqrtf(d_deg[i] + 1.0f);
}

// ---------------- FAST SGEMM: 128x128x16, 8x8 microtile, double-buffered ----
// Requires: K % 16 == 0, K % 4 == 0, N % 128 == 0. Row guard on M.
// Epilogue: v = acc * rowscale[row] (opt) + bias[col] (opt); relu (opt);
// store C, and optionally C2 (scatter-accumulator init = self-loop term).
__global__ __launch_bounds__(256, 1)
void fgemm_kernel(const float* __restrict__ A, const float* __restrict__ B,
                  const float* __restrict__ bias, const float* __restrict__ rowscale,
                  float* __restrict__ C, float* __restrict__ C2,
                  int M, int N, int K, int do_relu)
{
    const int BM = 128, BN = 128, BK = 16;
    __shared__ float As[2][BK][BM + 4];   // transposed A tile (padded vs STS conflicts)
    __shared__ float Bs[2][BK][BN];

    int tid = threadIdx.x;
    int tx  = tid & 15;          // 0..15 -> 8 cols each
    int ty  = tid >> 4;          // 0..15 -> 8 rows each
    int row0 = blockIdx.y * BM;
    int col0 = blockIdx.x * BN;

    float acc[8][8];
    #pragma unroll
    for (int i = 0; i < 8; i++)
        #pragma unroll
        for (int j = 0; j < 8; j++) acc[i][j] = 0.0f;

    const int ntiles = K / BK;
    float4 pa[2], pb[2];

    // ---- global load of tile kt into registers
    auto gload = [&](int kt) {
        int k0 = kt * BK;
        #pragma unroll
        for (int l = 0; l < 2; l++) {
            int idx = tid + l * 256;          // 0..511 (float4 units)
            int ar  = idx >> 2;               // 0..127
            int ac4 = idx & 3;                // 0..3
            int gr  = row0 + ar;
            if (gr < M)
                pa[l] = *(const float4*)&A[(size_t)gr * K + k0 + ac4 * 4];
            else
                pa[l] = make_float4(0.f, 0.f, 0.f, 0.f);
            int br  = idx >> 5;               // 0..15
            int bc4 = idx & 31;               // 0..31
            pb[l] = *(const float4*)&B[(size_t)(k0 + br) * N + col0 + bc4 * 4];
        }
    };
    // ---- store registers into smem buffer
    auto sstore = [&](int buf) {
        #pragma unroll
        for (int l = 0; l < 2; l++) {
            int idx = tid + l * 256;
            int ar  = idx >> 2;
            int ac4 = idx & 3;
            As[buf][ac4 * 4 + 0][ar] = pa[l].x;
            As[buf][ac4 * 4 + 1][ar] = pa[l].y;
            As[buf][ac4 * 4 + 2][ar] = pa[l].z;
            As[buf][ac4 * 4 + 3][ar] = pa[l].w;
            int br  = idx >> 5;
            int bc4 = idx & 31;
            *(float4*)&Bs[buf][br][bc4 * 4] = pb[l];
        }
    };

    gload(0);
    sstore(0);
    __syncthreads();

    for (int kt = 0; kt < ntiles; kt++) {
        int cur = kt & 1;
        if (kt + 1 < ntiles) gload(kt + 1);

        #pragma unroll
        for (int kk = 0; kk < BK; kk++) {
            float a[8], b[8];
            *(float4*)&a[0] = *(const float4*)&As[cur][kk][ty * 8];
            *(float4*)&a[4] = *(const float4*)&As[cur][kk][ty * 8 + 4];
            *(float4*)&b[0] = *(const float4*)&Bs[cur][kk][tx * 8];
            *(float4*)&b[4] = *(const float4*)&Bs[cur][kk][tx * 8 + 4];
            #pragma unroll
            for (int i = 0; i < 8; i++)
                #pragma unroll
                for (int j = 0; j < 8; j++)
                    acc[i][j] = fmaf(a[i], b[j], acc[i][j]);
        }

        if (kt + 1 < ntiles) {
            sstore(cur ^ 1);
            __syncthreads();
        }
    }

    // ---- epilogue
    float bvals[8];
    if (bias) {
        *(float4*)&bvals[0] = *(const float4*)&bias[col0 + tx * 8];
        *(float4*)&bvals[4] = *(const float4*)&bias[col0 + tx * 8 + 4];
    } else {
        #pragma unroll
        for (int j = 0; j < 8; j++) bvals[j] = 0.0f;
    }
    #pragma unroll
    for (int i = 0; i < 8; i++) {
        int gr = row0 + ty * 8 + i;
        if (gr >= M) continue;
        float rs = rowscale ? rowscale[gr] : 1.0f;
        float v[8];
        #pragma unroll
        for (int j = 0; j < 8; j++) {
            float t = acc[i][j] * rs + bvals[j];
            v[j] = do_relu ? fmaxf(t, 0.0f) : t;
        }
        size_t base = (size_t)gr * N + col0 + tx * 8;
        *(float4*)&C[base]     = *(float4*)&v[0];
        *(float4*)&C[base + 4] = *(float4*)&v[4];
        if (C2) {
            *(float4*)&C2[base]     = *(float4*)&v[0];
            *(float4*)&C2[base + 4] = *(float4*)&v[4];
        }
    }
}

// ---------------- generic (slow) SGEMM for irregular shapes (K=167) --------
template<int BM, int BN, int BK>
__global__ __launch_bounds__(256)
void sgemm_kernel(const float* __restrict__ A, const float* __restrict__ W,
                  const float* __restrict__ bias, const float* __restrict__ rowscale,
                  float* __restrict__ C, float* __restrict__ C2,
                  int M, int N, int K, int do_relu)
{
    __shared__ float As[BM][BK + 1];
    __shared__ float Bs[BK][BN + 1];
    const int TM = 4, TN = 4;
    int tid = threadIdx.x;
    int tx  = tid % (BN / TN);
    int ty  = tid / (BN / TN);
    int row0 = blockIdx.y * BM;
    int col0 = blockIdx.x * BN;

    float acc[TM][TN];
    #pragma unroll
    for (int i = 0; i < TM; i++)
        #pragma unroll
        for (int j = 0; j < TN; j++) acc[i][j] = 0.0f;

    for (int k0 = 0; k0 < K; k0 += BK) {
        for (int i = tid; i < BM * BK; i += 256) {
            int r = i / BK, c = i % BK;
            int gr = row0 + r, gc = k0 + c;
            As[r][c] = (gr < M && gc < K) ? A[(size_t)gr * K + gc] : 0.0f;
        }
        for (int i = tid; i < BK * BN; i += 256) {
            int r = i / BN, c = i % BN;
            int gr = k0 + r, gc = col0 + c;
            Bs[r][c] = (gr < K && gc < N) ? W[(size_t)gr * N + gc] : 0.0f;
        }
        __syncthreads();
        #pragma unroll
        for (int kk = 0; kk < BK; kk++) {
            float a[TM], b[TN];
            #pragma unroll
            for (int i = 0; i < TM; i++) a[i] = As[ty * TM + i][kk];
            #pragma unroll
            for (int j = 0; j < TN; j++) b[j] = Bs[kk][tx * TN + j];
            #pragma unroll
            for (int i = 0; i < TM; i++)
                #pragma unroll
                for (int j = 0; j < TN; j++) acc[i][j] += a[i] * b[j];
        }
        __syncthreads();
    }

    #pragma unroll
    for (int i = 0; i < TM; i++) {
        int gr = row0 + ty * TM + i;
        if (gr >= M) continue;
        float rs = rowscale ? rowscale[gr] : 1.0f;
        #pragma unroll
        for (int j = 0; j < TN; j++) {
            int gc = col0 + tx * TN + j;
            if (gc >= N) continue;
            float v = acc[i][j] * rs;
            if (bias) v += bias[gc];
            if (do_relu) v = fmaxf(v, 0.0f);
            C[(size_t)gr * N + gc] = v;
            if (C2) C2[(size_t)gr * N + gc] = v;
        }
    }
}

// ---------------- edge scatter: agg[dst] += g[src] ----------------
__global__ void scatter_kernel(const int* __restrict__ ei, int E, int C) {
    int gw   = (blockIdx.x * blockDim.x + threadIdx.x) >> 5;
    int lane = threadIdx.x & 31;
    int nw   = (gridDim.x * blockDim.x) >> 5;
    for (int e = gw; e < E; e += nw) {
        unsigned s = (unsigned)ei[e];
        unsigned d = (unsigned)ei[E + e];
        if (s >= N_NODES || d >= N_NODES) continue;
        const float4* gs = (const float4*)(d_h + (size_t)s * C);
        float* ad = d_agg + (size_t)d * C;
        int c4 = C >> 2;
        for (int c = lane; c < c4; c += 32) {
            float4 v = gs[c];
            float* p = ad + 4 * c;
            asm volatile("red.global.add.v4.f32 [%0], {%1, %2, %3, %4};"
                         :: "l"(p), "f"(v.x), "f"(v.y), "f"(v.z), "f"(v.w)
                         : "memory");
        }
    }
}

// ---------------- combine: x_next = relu(dinv*agg + b (+ res)) ----------------
__global__ void combine_kernel(const float* __restrict__ bias,
                               const float* __restrict__ res,
                               float* __restrict__ out, int C) {
    size_t i = (size_t)blockIdx.x * blockDim.x + threadIdx.x;
    size_t total = (size_t)N_NODES * C;
    if (i >= total) return;
    int row = (int)(i / C);
    int col = (int)(i % C);
    float v = d_dinv[row] * d_agg[i] + bias[col];
    if (res) v += res[i];
    out[i] = fmaxf(v, 0.0f);
}

// ---------------- fused softmax-attention + mean-pool accumulate ----------------
__global__ void pool_kernel(const int* __restrict__ batch) {
    int node = (blockIdx.x * blockDim.x + threadIdx.x) >> 5;
    int lane = threadIdx.x & 31;
    if (node >= N_NODES) return;
    const float* srow = d_h  + (size_t)node * 256;   // attention scores
    const float* xrow = d_xa + (size_t)node * 256;   // x3
    float vals[8];
    float m = -3.0e38f;
    #pragma unroll
    for (int j = 0; j < 8; j++) { vals[j] = srow[lane + 32 * j]; m = fmaxf(m, vals[j]); }
    #pragma unroll
    for (int off = 16; off; off >>= 1) m = fmaxf(m, __shfl_xor_sync(0xffffffffu, m, off));
    float ssum = 0.0f;
    #pragma unroll
    for (int j = 0; j < 8; j++) { vals[j] = __expf(vals[j] - m); ssum += vals[j]; }
    #pragma unroll
    for (int off = 16; off; off >>= 1) ssum += __shfl_xor_sync(0xffffffffu, ssum, off);
    float inv = 1.0f / ssum;
    unsigned b = (unsigned)batch[node];
    if (b >= N_GRAPHS) return;
    float* orow = d_sums + (size_t)b * 256;
    #pragma unroll
    for (int j = 0; j < 8; j++) {
        atomicAdd(orow + lane + 32 * j, vals[j] * inv * xrow[lane + 32 * j]);
    }
    if (lane == 0) atomicAdd(&d_cnt[b], 1.0f);
}

// ---------------- final: out = (pooled + fp + fg) @ Wfc + bfc ----------------
__global__ void final_kernel(const float* __restrict__ Wfc,
                             const float* __restrict__ bfc,
                             float* __restrict__ out) {
    int b    = (blockIdx.x * blockDim.x + threadIdx.x) >> 5;
    int lane = threadIdx.x & 31;
    if (b >= N_GRAPHS) return;
    float invc = 1.0f / fmaxf(d_cnt[b], 1.0f);
    float acc = 0.0f;
    #pragma unroll
    for (int j = lane; j < 256; j += 32) {
        float v = d_sums[b * 256 + j] * invc + d_fp[b * 256 + j] + d_fg[b * 256 + j];
        acc += v * Wfc[j];
    }
    #pragma unroll
    for (int off = 16; off; off >>= 1) acc += __shfl_xor_sync(0xffffffffu, acc, off);
    if (lane == 0) out[b] = acc + bfc[0];
}

// ---------------- launch ----------------
extern "C" void kernel_launch(void* const* d_in, const int* in_sizes, int n_in,
                              void* d_out, int out_size) {
    const float* x     = (const float*)d_in[0];
    const int*   ei    = (const int*)d_in[1];     // int32 (JAX x64 disabled)
    const int*   batch = (const int*)d_in[2];     // int32
    const float* fpf = (const float*)d_in[3];
    const float* fgr = (const float*)d_in[4];
    const float* W1  = (const float*)d_in[5],  *b1  = (const float*)d_in[6];
    const float* W2  = (const float*)d_in[7],  *b2  = (const float*)d_in[8];
    const float* W3  = (const float*)d_in[9],  *b3  = (const float*)d_in[10];
    const float* Wr1 = (const float*)d_in[11], *br1 = (const float*)d_in[12];
    const float* Wr2 = (const float*)d_in[13], *br2 = (const float*)d_in[14];
    const float* Wfp = (const float*)d_in[15], *bfp = (const float*)d_in[16];
    const float* Wfg = (const float*)d_in[17], *bfg = (const float*)d_in[18];
    const float* attn_W = (const float*)d_in[19];
    const float* Wfc = (const float*)d_in[20], *bfc = (const float*)d_in[21];
    float* out = (float*)d_out;
    int E = in_sizes[1] / 2;

    float *ph, *pagg, *pres, *pxa, *pxb, *pdinv, *pfp, *pfg;
    cudaGetSymbolAddress((void**)&ph,   d_h);
    cudaGetSymbolAddress((void**)&pagg, d_agg);
    cudaGetSymbolAddress((void**)&pres, d_res);
    cudaGetSymbolAddress((void**)&pxa,  d_xa);
    cudaGetSymbolAddress((void**)&pxb,  d_xb);
    cudaGetSymbolAddress((void**)&pdinv, d_dinv);
    cudaGetSymbolAddress((void**)&pfp,  d_fp);
    cudaGetSymbolAddress((void**)&pfg,  d_fg);

    const int T = 256;
    auto cdiv = [](int a, int b) { return (a + b - 1) / b; };

    zero_kernel<<<cdiv(N_NODES + N_GRAPHS * MAXC + N_GRAPHS, T), T>>>();
    deg_kernel<<<cdiv(E, T), T>>>(ei, E);
    dinv_kernel<<<cdiv(N_NODES, T), T>>>();

    dim3 gN128(1, cdiv(N_NODES, 128));      // N=128
    dim3 gN256(2, cdiv(N_NODES, 128));      // N=256
    dim3 gB256f(2, cdiv(N_GRAPHS, 128));    // fp branch (fast path)
    dim3 gB256s(256 / 64, cdiv(N_GRAPHS, 64)); // fg branch (slow path, K=167)
    int scatterBlocks = cdiv(E, 8);         // one warp per edge

    // ---- Layer 1: g1 = dinv*(x@W1); scatter; x1 = relu(dinv*agg + b1)
    fgemm_kernel<<<gN128, T>>>(x, W1, nullptr, pdinv, ph, pagg,
                               N_NODES, 128, 64, 0);
    scatter_kernel<<<scatterBlocks, T>>>(ei, E, 128);
    combine_kernel<<<cdiv(N_NODES * 128, T), T>>>(b1, nullptr, pxa, 128);

    // ---- Layer 2
    fgemm_kernel<<<gN256, T>>>(pxa, Wr1, br1, nullptr, pres, nullptr,
                               N_NODES, 256, 128, 0);
    fgemm_kernel<<<gN256, T>>>(pxa, W2, nullptr, pdinv, ph, pagg,
                               N_NODES, 256, 128, 0);
    scatter_kernel<<<scatterBlocks, T>>>(ei, E, 256);
    combine_kernel<<<cdiv(N_NODES * 256, T), T>>>(b2, pres, pxb, 256);

    // ---- Layer 3
    fgemm_kernel<<<gN256, T>>>(pxb, Wr2, br2, nullptr, pres, nullptr,
                               N_NODES, 256, 256, 0);
    fgemm_kernel<<<gN256, T>>>(pxb, W3, nullptr, pdinv, ph, pagg,
                               N_NODES, 256, 256, 0);
    scatter_kernel<<<scatterBlocks, T>>>(ei, E, 256);
    combine_kernel<<<cdiv(N_NODES * 256, T), T>>>(b3, pres, pxa, 256);

    // ---- attention scores: s = x3 @ attn_W  (into d_h)
    fgemm_kernel<<<gN256, T>>>(pxa, attn_W, nullptr, nullptr, ph, nullptr,
                               N_NODES, 256, 256, 0);

    // ---- fingerprint / func-group branches
    fgemm_kernel<<<gB256f, T>>>(fpf, Wfp, bfp, nullptr, pfp, nullptr,
                                N_GRAPHS, 256, 2048, 1);
    sgemm_kernel<64,64,16><<<gB256s, T>>>(fgr, Wfg, bfg, nullptr, pfg, nullptr,
                                          N_GRAPHS, 256, 167, 1);

    // ---- softmax-attention mean pool + final projection
    pool_kernel<<<cdiv(N_NODES * 32, T), T>>>(batch);
    final_kernel<<<cdiv(N_GRAPHS * 32, T), T>>>(Wfc, bfc, out);
}